// round 9
// baseline (speedup 1.0000x reference)
#include <cuda_runtime.h>
#include <cuda_bf16.h>
#include <math.h>
#include <stdint.h>

// z (16,128,64,64) fp32, codebook (1024,128) fp32
#define C      128
#define KC     1024
#define BATCH  16
#define HW     4096
#define NTOT   (BATCH * HW)     // 65536
#define M_ZQ   (NTOT * C)       // 8388608
#define MT     128              // rows per MMA CTA
#define NT     32               // codes per chunk
#define NCH    (KC / NT)        // 32 chunks
#define GRID_MMA (NTOT / MT)    // 512
#define TN     64               // rows per rescore block
#define NBLK   (NTOT / TN)      // 1024
#define MARGIN 4e-3f            // >> 2x worst-case bf16 score error (~1.1e-3)
#define MAXCAND 32              // global per-row candidate cap
#define LCAND   8               // per-lane local cap
#define ZS     136              // smem halfs per row (128 + 8 pad)

// Scratch (no allocs allowed)
__device__ float          d_enorm[KC];
__device__ int            d_used[KC];
__device__ float          d_partials[NBLK];
__device__ unsigned short d_cand[NTOT * MAXCAND];
__device__ int            d_ccnt[NTOT];

// ---------------------------------------------------------------------------
// m16n8k16 bf16 MMA (standard PTX, works on plain sm_103 target)
__device__ __forceinline__ void mma16816(float* d, const uint32_t* a,
                                         uint32_t b0, uint32_t b1) {
    asm volatile(
        "mma.sync.aligned.m16n8k16.row.col.f32.bf16.bf16.f32 "
        "{%0,%1,%2,%3}, {%4,%5,%6,%7}, {%8,%9}, {%0,%1,%2,%3};"
        : "+f"(d[0]), "+f"(d[1]), "+f"(d[2]), "+f"(d[3])
        : "r"(a[0]), "r"(a[1]), "r"(a[2]), "r"(a[3]), "r"(b0), "r"(b1));
}

// ---------------------------------------------------------------------------
// Prep: ||e_k||^2 serial (ref-style rounding) + zero usage
__global__ void vq_prep(const float* __restrict__ cb) {
    int k = blockIdx.x * 256 + threadIdx.x;
    const float* row = cb + k * C;
    float s = 0.f;
    for (int c = 0; c < C; c++) {
        float v = row[c];
        s = __fadd_rn(s, __fmul_rn(v, v));
    }
    d_enorm[k] = s;
    d_used[k] = 0;
}

// ---------------------------------------------------------------------------
// Tensor-pipe approximate scores + per-row candidate collection.
// 128 threads (4 warps); warp w owns rows w*32..w*32+31 (2 m16 tiles).
__global__ void __launch_bounds__(128)
vq_mma(const float* __restrict__ z, const float* __restrict__ cb) {
    __shared__ __nv_bfloat16 z_s[MT * ZS];   // 34816 B
    __shared__ __nv_bfloat16 b_s[NT * ZS];   // 8704 B
    __shared__ float en_s[NT];

    const int tid  = threadIdx.x;
    const int lane = tid & 31;
    const int wid  = tid >> 5;
    const int g    = lane >> 2;       // fragment group (row within tile)
    const int tq   = lane & 3;        // thread-in-quad (col pair / k pair)
    const int n0   = blockIdx.x * MT;
    const int b    = n0 >> 12;
    const int hw0  = n0 & (HW - 1);
    const float* zb = z + (size_t)b * C * HW + hw0;

    // ---- stage z tile as bf16 [row][c] ----
    for (int p = tid; p < MT * (C / 2); p += 128) {
        int row = p & 127;            // coalesced along hw
        int cp  = p >> 7;             // c pair
        float a0 = zb[(size_t)(2 * cp)     * HW + row];
        float a1 = zb[(size_t)(2 * cp + 1) * HW + row];
        __nv_bfloat162 v = __floats2bfloat162_rn(a0, a1);
        *(uint32_t*)&z_s[row * ZS + 2 * cp] = *(uint32_t*)&v;
    }
    __syncthreads();

    // ---- A fragments, register resident: 2 m-tiles x 8 k-tiles x 4 regs ----
    uint32_t afr[2][8][4];
#pragma unroll
    for (int mt = 0; mt < 2; mt++) {
        const int r = wid * 32 + mt * 16 + g;
#pragma unroll
        for (int kt = 0; kt < 8; kt++) {
            const int k = kt * 16 + tq * 2;
            afr[mt][kt][0] = *(uint32_t*)&z_s[r * ZS + k];
            afr[mt][kt][1] = *(uint32_t*)&z_s[(r + 8) * ZS + k];
            afr[mt][kt][2] = *(uint32_t*)&z_s[r * ZS + k + 8];
            afr[mt][kt][3] = *(uint32_t*)&z_s[(r + 8) * ZS + k + 8];
        }
    }

    // per-lane state: 4 owned rows (slot = mt*2 + {0:g, 1:g+8})
    float runmin[4] = {INFINITY, INFINITY, INFINITY, INFINITY};
    int   cnt[4]    = {0, 0, 0, 0};
    unsigned short candl[4][LCAND];

    // ---- software-pipelined B: prefetch chunk's fp32 to regs, cvt on store ----
    float2 pre[16];
#pragma unroll
    for (int it = 0; it < 16; it++) {
        int p = it * 128 + tid;
        int row = p >> 6, cp = p & 63;
        pre[it] = *(const float2*)&cb[(size_t)row * C + 2 * cp];
    }
    float enp = (tid < NT) ? d_enorm[tid] : 0.f;

    for (int ch = 0; ch < NCH; ch++) {
        // store staged chunk to smem
#pragma unroll
        for (int it = 0; it < 16; it++) {
            int p = it * 128 + tid;
            int row = p >> 6, cp = p & 63;
            __nv_bfloat162 v = __floats2bfloat162_rn(pre[it].x, pre[it].y);
            *(uint32_t*)&b_s[row * ZS + 2 * cp] = *(uint32_t*)&v;
        }
        if (tid < NT) en_s[tid] = enp;
        __syncthreads();

        // issue next chunk's loads (hide L2 latency under MMA)
        if (ch + 1 < NCH) {
            const int k0n = (ch + 1) * NT;
#pragma unroll
            for (int it = 0; it < 16; it++) {
                int p = it * 128 + tid;
                int row = p >> 6, cp = p & 63;
                pre[it] = *(const float2*)&cb[(size_t)(k0n + row) * C + 2 * cp];
            }
            if (tid < NT) enp = d_enorm[k0n + tid];
        }

        const int k0 = ch * NT;
        const float en0 = en_s[2 * tq];     // cols owned by this lane (per n-tile base)
#pragma unroll
        for (int nt = 0; nt < 4; nt++) {
            const int nb = nt * 8;
            const float e0 = en_s[nb + 2 * tq];
            const float e1 = en_s[nb + 2 * tq + 1];
            uint32_t badr = (nb + g) * ZS + tq * 2;
            float acc[2][4] = {{0, 0, 0, 0}, {0, 0, 0, 0}};
#pragma unroll
            for (int kt = 0; kt < 8; kt++) {
                uint32_t b0 = *(uint32_t*)&b_s[badr + kt * 16];
                uint32_t b1 = *(uint32_t*)&b_s[badr + kt * 16 + 8];
                mma16816(acc[0], afr[0][kt], b0, b1);
                mma16816(acc[1], afr[1][kt], b0, b1);
            }
            const int col0 = k0 + nb + 2 * tq;
#pragma unroll
            for (int mt = 0; mt < 2; mt++) {
#pragma unroll
                for (int e = 0; e < 4; e++) {
                    const int slot = mt * 2 + (e >> 1);
                    const float en = (e & 1) ? e1 : e0;
                    const int  col = col0 + (e & 1);
                    float s = en - 2.f * acc[mt][e];
                    if (s < runmin[slot] + MARGIN) {
                        if (cnt[slot] < LCAND)
                            candl[slot][cnt[slot]] = (unsigned short)col;
                        cnt[slot]++;
                        if (s < runmin[slot]) runmin[slot] = s;
                    }
                }
            }
        }
        (void)en0;
        __syncthreads();   // b_s/en_s reuse
    }

    // ---- quad merge + global write ----
    const int qbase = lane & ~3;
#pragma unroll
    for (int slot = 0; slot < 4; slot++) {
        const int mt  = slot >> 1;
        const int sub = slot & 1;
        const int n   = n0 + wid * 32 + mt * 16 + g + sub * 8;
        int myc = (cnt[slot] > LCAND) ? 100 : cnt[slot];
        int total = 0, off = 0;
#pragma unroll
        for (int j = 0; j < 4; j++) {
            int cj = __shfl_sync(0xffffffff, myc, qbase + j);
            total += cj;
            if (j < tq) off += cj;
        }
        if (total <= MAXCAND) {
            for (int i = 0; i < myc; i++)
                d_cand[(size_t)n * MAXCAND + off + i] = candl[slot][i];
        }
        if (tq == 0) d_ccnt[n] = total;
    }
}

// ---------------------------------------------------------------------------
// Exact rescore (bit-identical to the round-5 passing arithmetic) + gather +
// straight-through output + loss partial + usage.
__global__ void __launch_bounds__(128)
vq_rescore(const float* __restrict__ z, const float* __restrict__ cb,
           float* __restrict__ out) {
    __shared__ float z_s[C * TN];
    __shared__ float zn_s[TN];
    __shared__ int   idx_s[TN];
    __shared__ float red[128];

    const int tid = threadIdx.x;
    const int n0  = blockIdx.x * TN;
    const int b   = n0 >> 12;
    const int hw0 = n0 & (HW - 1);
    const float* zb = z + (size_t)b * C * HW + hw0;

    for (int v = tid; v < C * TN / 4; v += 128) {
        int c  = v >> 4;
        int i4 = v & 15;
        float4 t = *reinterpret_cast<const float4*>(zb + (size_t)c * HW + i4 * 4);
        *reinterpret_cast<float4*>(&z_s[c * TN + i4 * 4]) = t;
    }
    __syncthreads();

    if (tid < TN) {
        float s = 0.f;
        for (int c = 0; c < C; c++) {
            float v = z_s[c * TN + tid];
            s = __fadd_rn(s, __fmul_rn(v, v));
        }
        zn_s[tid] = s;
    }
    __syncthreads();

    if (tid < TN) {
        const int n   = n0 + tid;
        const int cnt = d_ccnt[n];
        const float zn = zn_s[tid];
        float best = INFINITY;
        int   bk   = KC;
        if (cnt <= MAXCAND) {
            for (int i = 0; i < cnt; i++) {
                int k = d_cand[(size_t)n * MAXCAND + i];
                const float* e = cb + (size_t)k * C;
                float dot = 0.f;
                for (int c = 0; c < C; c++)
                    dot = fmaf(__ldg(&e[c]), z_s[c * TN + tid], dot);
                float t1 = __fadd_rn(zn, __ldg(&d_enorm[k]));
                float s  = __fadd_rn(t1, __fmul_rn(-2.f, dot));
                // jnp.argmin: smallest index among ties (candidates unordered)
                if (s < best || (s == best && k < bk)) { best = s; bk = k; }
            }
        } else {
            for (int k = 0; k < KC; k++) {           // overflow: exact full scan
                const float* e = cb + (size_t)k * C;
                float dot = 0.f;
                for (int c = 0; c < C; c++)
                    dot = fmaf(__ldg(&e[c]), z_s[c * TN + tid], dot);
                float t1 = __fadd_rn(zn, __ldg(&d_enorm[k]));
                float s  = __fadd_rn(t1, __fmul_rn(-2.f, dot));
                if (s < best) { best = s; bk = k; }  // ascending: first min wins
            }
        }
        idx_s[tid] = bk;
        d_used[bk] = 1;
    }
    __syncthreads();

    float* ob = out + (size_t)b * C * HW + hw0;
    float lsum = 0.f;
    for (int p = tid; p < TN * C; p += 128) {
        int row = p & (TN - 1);
        int c   = p >> 6;
        float zq = __ldg(&cb[(size_t)idx_s[row] * C + c]);
        float zv = z_s[c * TN + row];
        float d  = __fadd_rn(zq, -zv);
        ob[(size_t)c * HW + row] = __fadd_rn(zv, d);
        lsum += d * d;
    }

    red[tid] = lsum;
    __syncthreads();
#pragma unroll
    for (int s = 64; s > 0; s >>= 1) {
        if (tid < s) red[tid] += red[tid + s];
        __syncthreads();
    }
    if (tid == 0) d_partials[blockIdx.x] = red[0];
}

// ---------------------------------------------------------------------------
__global__ void vq_final(float* __restrict__ out, int out_size) {
    __shared__ float fred[256];
    __shared__ int   ired[256];
    const int t = threadIdx.x;

    float fs = 0.f;
#pragma unroll
    for (int p = t; p < NBLK; p += 256) fs += d_partials[p];
    int cnt = 0;
#pragma unroll
    for (int k = t; k < KC; k += 256) cnt += d_used[k];
    fred[t] = fs;
    ired[t] = cnt;
    __syncthreads();
#pragma unroll
    for (int s = 128; s > 0; s >>= 1) {
        if (t < s) { fred[t] += fred[t + s]; ired[t] += ired[t + s]; }
        __syncthreads();
    }
    if (t == 0 && out_size >= M_ZQ + 2) {
        float mse = fred[0] / (float)((size_t)NTOT * C);
        out[M_ZQ]     = 1.25f * mse;
        out[M_ZQ + 1] = (float)ired[0] / (float)KC;
    }
}

// ---------------------------------------------------------------------------
extern "C" void kernel_launch(void* const* d_in, const int* in_sizes, int n_in,
                              void* d_out, int out_size) {
    const float* z;
    const float* cb;
    if (in_sizes[0] == KC * C) {
        cb = (const float*)d_in[0];
        z  = (const float*)d_in[1];
    } else {
        z  = (const float*)d_in[0];
        cb = (const float*)d_in[1];
    }
    float* out = (float*)d_out;

    vq_prep<<<KC / 256, 256>>>(cb);
    vq_mma<<<GRID_MMA, 128>>>(z, cb);
    vq_rescore<<<NBLK, 128>>>(z, cb, out);
    vq_final<<<1, 256>>>(out, out_size);
}

// round 10
// speedup vs baseline: 1.4199x; 1.4199x over previous
#include <cuda_runtime.h>
#include <cuda_bf16.h>
#include <math.h>
#include <stdint.h>

// z (16,128,64,64) fp32, codebook (1024,128) fp32
#define C      128
#define KC     1024
#define BATCH  16
#define HW     4096
#define NTOT   (BATCH * HW)     // 65536
#define M_ZQ   (NTOT * C)       // 8388608
#define MT     128              // rows per MMA CTA
#define NT     32               // codes per chunk
#define NCH    (KC / NT)        // 32 chunks
#define GRID_MMA (NTOT / MT)    // 512
#define TN     64               // rows per rescore block
#define NBLK   (NTOT / TN)      // 1024
#define MARGIN 2e-3f            // > 2x worst-case bf16 score error (1.13e-3 bound)
#define MAXCAND 32              // global per-row candidate cap
#define LCAND   8               // per-lane local cap (with compaction)
#define ZS     136              // smem halfs per row (128 + 8 pad)

// Scratch (no allocs allowed)
__device__ float          d_enorm[KC];
__device__ int            d_used[KC];
__device__ float          d_partials[NBLK];
__device__ unsigned short d_cand[NTOT * MAXCAND];
__device__ int            d_ccnt[NTOT];

// ---------------------------------------------------------------------------
// m16n8k16 bf16 MMA (plain PTX, works on sm_103 base target)
__device__ __forceinline__ void mma16816(float* d, const uint32_t* a,
                                         uint32_t b0, uint32_t b1) {
    asm volatile(
        "mma.sync.aligned.m16n8k16.row.col.f32.bf16.bf16.f32 "
        "{%0,%1,%2,%3}, {%4,%5,%6,%7}, {%8,%9}, {%0,%1,%2,%3};"
        : "+f"(d[0]), "+f"(d[1]), "+f"(d[2]), "+f"(d[3])
        : "r"(a[0]), "r"(a[1]), "r"(a[2]), "r"(a[3]), "r"(b0), "r"(b1));
}

// Candidate insert with compaction-on-full (runmin monotonically decreases,
// so stale records get filtered out; overflow only if >LCAND simultaneously
// viable, which is ~never at MARGIN=2e-3).
__device__ __forceinline__ void cand_insert(float s, int col, float* sc,
                                            unsigned short* cd, int& cnt,
                                            float& runmin, bool& ovf) {
    if (s < runmin + MARGIN) {
        if (cnt == LCAND) {
            int w = 0;
            for (int i = 0; i < LCAND; i++) {
                if (sc[i] < runmin + MARGIN) { sc[w] = sc[i]; cd[w] = cd[i]; w++; }
            }
            cnt = w;
        }
        if (cnt < LCAND) { sc[cnt] = s; cd[cnt] = (unsigned short)col; cnt++; }
        else ovf = true;
        if (s < runmin) runmin = s;
    }
}

// ---------------------------------------------------------------------------
// Prep: ||e_k||^2 serial (ref-style rounding) + zero usage. 32 blocks for MLP.
__global__ void vq_prep(const float* __restrict__ cb) {
    int k = blockIdx.x * 32 + threadIdx.x;
    const float* row = cb + k * C;
    float s = 0.f;
#pragma unroll
    for (int c = 0; c < C; c++) {
        float v = row[c];
        s = __fadd_rn(s, __fmul_rn(v, v));
    }
    d_enorm[k] = s;
    if (blockIdx.x < 32) d_used[k] = 0;
}

// ---------------------------------------------------------------------------
// Tensor-pipe approximate scores + per-row candidate collection.
// 128 threads (4 warps); warp w owns rows w*32..w*32+31 (2 m16 tiles).
__global__ void __launch_bounds__(128)
vq_mma(const float* __restrict__ z, const float* __restrict__ cb) {
    __shared__ __nv_bfloat16 z_s[MT * ZS];   // 34816 B
    __shared__ __nv_bfloat16 b_s[NT * ZS];   // 8704 B
    __shared__ float en_s[NT];

    const int tid  = threadIdx.x;
    const int lane = tid & 31;
    const int wid  = tid >> 5;
    const int g    = lane >> 2;       // fragment group (row within tile)
    const int tq   = lane & 3;        // thread-in-quad
    const int n0   = blockIdx.x * MT;
    const int b    = n0 >> 12;
    const int hw0  = n0 & (HW - 1);
    const float* zb = z + (size_t)b * C * HW + hw0;

    // ---- stage z tile as bf16 [row][c] ----
    for (int p = tid; p < MT * (C / 2); p += 128) {
        int row = p & 127;            // coalesced along hw
        int cp  = p >> 7;             // c pair
        float a0 = zb[(size_t)(2 * cp)     * HW + row];
        float a1 = zb[(size_t)(2 * cp + 1) * HW + row];
        __nv_bfloat162 v = __floats2bfloat162_rn(a0, a1);
        *(uint32_t*)&z_s[row * ZS + 2 * cp] = *(uint32_t*)&v;
    }
    __syncthreads();

    // ---- A fragments, register resident: 2 m-tiles x 8 k-tiles x 4 regs ----
    uint32_t afr[2][8][4];
#pragma unroll
    for (int mt = 0; mt < 2; mt++) {
        const int r = wid * 32 + mt * 16 + g;
#pragma unroll
        for (int kt = 0; kt < 8; kt++) {
            const int k = kt * 16 + tq * 2;
            afr[mt][kt][0] = *(uint32_t*)&z_s[r * ZS + k];
            afr[mt][kt][1] = *(uint32_t*)&z_s[(r + 8) * ZS + k];
            afr[mt][kt][2] = *(uint32_t*)&z_s[r * ZS + k + 8];
            afr[mt][kt][3] = *(uint32_t*)&z_s[(r + 8) * ZS + k + 8];
        }
    }

    // per-lane state: 4 owned rows (slot = mt*2 + (e>>1))
    float runmin[4] = {INFINITY, INFINITY, INFINITY, INFINITY};
    int   cnt[4]    = {0, 0, 0, 0};
    bool  ovf[4]    = {false, false, false, false};
    float          sc[4][LCAND];
    unsigned short candl[4][LCAND];

    // ---- software-pipelined B: prefetch chunk's fp32 to regs, cvt on store ----
    float2 pre[16];
#pragma unroll
    for (int it = 0; it < 16; it++) {
        int p = it * 128 + tid;
        int row = p >> 6, cp = p & 63;
        pre[it] = *(const float2*)&cb[(size_t)row * C + 2 * cp];
    }
    float enp = (tid < NT) ? d_enorm[tid] : 0.f;

    for (int ch = 0; ch < NCH; ch++) {
#pragma unroll
        for (int it = 0; it < 16; it++) {
            int p = it * 128 + tid;
            int row = p >> 6, cp = p & 63;
            __nv_bfloat162 v = __floats2bfloat162_rn(pre[it].x, pre[it].y);
            *(uint32_t*)&b_s[row * ZS + 2 * cp] = *(uint32_t*)&v;
        }
        if (tid < NT) en_s[tid] = enp;
        __syncthreads();

        // issue next chunk's loads (hide L2 latency under MMA)
        if (ch + 1 < NCH) {
            const int k0n = (ch + 1) * NT;
#pragma unroll
            for (int it = 0; it < 16; it++) {
                int p = it * 128 + tid;
                int row = p >> 6, cp = p & 63;
                pre[it] = *(const float2*)&cb[(size_t)(k0n + row) * C + 2 * cp];
            }
            if (tid < NT) enp = d_enorm[k0n + tid];
        }

        const int k0 = ch * NT;
#pragma unroll
        for (int nt = 0; nt < 4; nt++) {
            const int nb = nt * 8;
            const float e0 = en_s[nb + 2 * tq];
            const float e1 = en_s[nb + 2 * tq + 1];
            uint32_t badr = (nb + g) * ZS + tq * 2;
            float acc[2][4] = {{0, 0, 0, 0}, {0, 0, 0, 0}};
#pragma unroll
            for (int kt = 0; kt < 8; kt++) {
                uint32_t b0 = *(uint32_t*)&b_s[badr + kt * 16];
                uint32_t b1 = *(uint32_t*)&b_s[badr + kt * 16 + 8];
                mma16816(acc[0], afr[0][kt], b0, b1);
                mma16816(acc[1], afr[1][kt], b0, b1);
            }
            const int col0 = k0 + nb + 2 * tq;
#pragma unroll
            for (int mt = 0; mt < 2; mt++) {
#pragma unroll
                for (int e = 0; e < 4; e++) {
                    const int slot = mt * 2 + (e >> 1);
                    const float en = (e & 1) ? e1 : e0;
                    float s = en - 2.f * acc[mt][e];
                    cand_insert(s, col0 + (e & 1), sc[slot], candl[slot],
                                cnt[slot], runmin[slot], ovf[slot]);
                }
            }
        }
        __syncthreads();   // b_s/en_s reuse
    }

    // ---- final compaction against terminal runmin, then quad merge ----
    const int qbase = lane & ~3;
#pragma unroll
    for (int slot = 0; slot < 4; slot++) {
        int w = 0;
        for (int i = 0; i < cnt[slot]; i++) {
            if (sc[slot][i] < runmin[slot] + MARGIN) {
                sc[slot][w] = sc[slot][i];
                candl[slot][w] = candl[slot][i];
                w++;
            }
        }
        cnt[slot] = w;

        const int mt  = slot >> 1;
        const int sub = slot & 1;
        const int n   = n0 + wid * 32 + mt * 16 + g + sub * 8;
        int myc = ovf[slot] ? 100 : cnt[slot];
        int total = 0, off = 0;
#pragma unroll
        for (int j = 0; j < 4; j++) {
            int cj = __shfl_sync(0xffffffff, myc, qbase + j);
            total += cj;
            if (j < tq) off += cj;
        }
        if (total <= MAXCAND) {
            for (int i = 0; i < myc; i++)
                d_cand[(size_t)n * MAXCAND + off + i] = candl[slot][i];
        }
        if (tq == 0) d_ccnt[n] = total;
    }
}

// ---------------------------------------------------------------------------
// Exact rescore (bit-identical to the round-5 passing arithmetic) + gather +
// straight-through output + loss partial + usage.
__global__ void __launch_bounds__(128)
vq_rescore(const float* __restrict__ z, const float* __restrict__ cb,
           float* __restrict__ out) {
    __shared__ float z_s[C * TN];
    __shared__ float zn_s[TN];
    __shared__ int   idx_s[TN];
    __shared__ float red[128];

    const int tid = threadIdx.x;
    const int n0  = blockIdx.x * TN;
    const int b   = n0 >> 12;
    const int hw0 = n0 & (HW - 1);
    const float* zb = z + (size_t)b * C * HW + hw0;

    for (int v = tid; v < C * TN / 4; v += 128) {
        int c  = v >> 4;
        int i4 = v & 15;
        float4 t = *reinterpret_cast<const float4*>(zb + (size_t)c * HW + i4 * 4);
        *reinterpret_cast<float4*>(&z_s[c * TN + i4 * 4]) = t;
    }
    __syncthreads();

    if (tid < TN) {
        float s = 0.f;
        for (int c = 0; c < C; c++) {
            float v = z_s[c * TN + tid];
            s = __fadd_rn(s, __fmul_rn(v, v));
        }
        zn_s[tid] = s;
    }
    __syncthreads();

    if (tid < TN) {
        const int n   = n0 + tid;
        const int cnt = d_ccnt[n];
        const float zn = zn_s[tid];
        float best = INFINITY;
        int   bk   = KC;
        if (cnt <= MAXCAND) {
            for (int i = 0; i < cnt; i++) {
                int k = d_cand[(size_t)n * MAXCAND + i];
                const float* e = cb + (size_t)k * C;
                float dot = 0.f;
                for (int c = 0; c < C; c++)
                    dot = fmaf(__ldg(&e[c]), z_s[c * TN + tid], dot);
                float t1 = __fadd_rn(zn, __ldg(&d_enorm[k]));
                float s  = __fadd_rn(t1, __fmul_rn(-2.f, dot));
                // jnp.argmin: smallest index among ties (candidates unordered)
                if (s < best || (s == best && k < bk)) { best = s; bk = k; }
            }
        } else {
            for (int k = 0; k < KC; k++) {           // overflow: exact full scan
                const float* e = cb + (size_t)k * C;
                float dot = 0.f;
                for (int c = 0; c < C; c++)
                    dot = fmaf(__ldg(&e[c]), z_s[c * TN + tid], dot);
                float t1 = __fadd_rn(zn, __ldg(&d_enorm[k]));
                float s  = __fadd_rn(t1, __fmul_rn(-2.f, dot));
                if (s < best) { best = s; bk = k; }  // ascending: first min wins
            }
        }
        idx_s[tid] = bk;
        d_used[bk] = 1;
    }
    __syncthreads();

    float* ob = out + (size_t)b * C * HW + hw0;
    float lsum = 0.f;
    for (int p = tid; p < TN * C; p += 128) {
        int row = p & (TN - 1);
        int c   = p >> 6;
        float zq = __ldg(&cb[(size_t)idx_s[row] * C + c]);
        float zv = z_s[c * TN + row];
        float d  = __fadd_rn(zq, -zv);
        ob[(size_t)c * HW + row] = __fadd_rn(zv, d);
        lsum += d * d;
    }

    red[tid] = lsum;
    __syncthreads();
#pragma unroll
    for (int s = 64; s > 0; s >>= 1) {
        if (tid < s) red[tid] += red[tid + s];
        __syncthreads();
    }
    if (tid == 0) d_partials[blockIdx.x] = red[0];
}

// ---------------------------------------------------------------------------
__global__ void vq_final(float* __restrict__ out, int out_size) {
    __shared__ float fred[256];
    __shared__ int   ired[256];
    const int t = threadIdx.x;

    float fs = 0.f;
#pragma unroll
    for (int p = t; p < NBLK; p += 256) fs += d_partials[p];
    int cnt = 0;
#pragma unroll
    for (int k = t; k < KC; k += 256) cnt += d_used[k];
    fred[t] = fs;
    ired[t] = cnt;
    __syncthreads();
#pragma unroll
    for (int s = 128; s > 0; s >>= 1) {
        if (t < s) { fred[t] += fred[t + s]; ired[t] += ired[t + s]; }
        __syncthreads();
    }
    if (t == 0 && out_size >= M_ZQ + 2) {
        float mse = fred[0] / (float)((size_t)NTOT * C);
        out[M_ZQ]     = 1.25f * mse;
        out[M_ZQ + 1] = (float)ired[0] / (float)KC;
    }
}

// ---------------------------------------------------------------------------
extern "C" void kernel_launch(void* const* d_in, const int* in_sizes, int n_in,
                              void* d_out, int out_size) {
    const float* z;
    const float* cb;
    if (in_sizes[0] == KC * C) {
        cb = (const float*)d_in[0];
        z  = (const float*)d_in[1];
    } else {
        z  = (const float*)d_in[0];
        cb = (const float*)d_in[1];
    }
    float* out = (float*)d_out;

    vq_prep<<<KC / 32, 32>>>(cb);
    vq_mma<<<GRID_MMA, 128>>>(z, cb);
    vq_rescore<<<NBLK, 128>>>(z, cb, out);
    vq_final<<<1, 256>>>(out, out_size);
}

// round 12
// speedup vs baseline: 9.8746x; 6.9543x over previous
#include <cuda_runtime.h>
#include <cuda_bf16.h>
#include <math.h>
#include <stdint.h>

// z (16,128,64,64) fp32, codebook (1024,128) fp32
#define C      128
#define KC     1024
#define BATCH  16
#define HW     4096
#define NTOT   (BATCH * HW)     // 65536
#define M_ZQ   (NTOT * C)       // 8388608
#define MT     128              // rows per MMA CTA
#define NT     32               // codes per chunk
#define NCH    (KC / NT)        // 32 chunks
#define GRID_MMA (NTOT / MT)    // 512
#define TN     64               // rows per rescore block
#define NBLK   (NTOT / TN)      // 1024
#define MARGIN 1e-3f            // > 2x worst-case bf16 score error (~4.4e-4)
#define MAXCAND 32              // global per-row cap (= warp size for rescore)
#define LCAND   8               // per-lane local cap (with compaction)
#define ZS     136              // smem halfs per row (128 + 8 pad)

// Scratch (no allocs allowed)
__device__ float          d_enorm[KC];
__device__ int            d_used[KC];
__device__ float          d_partials[NBLK];
__device__ unsigned short d_cand[NTOT * MAXCAND];
__device__ int            d_ccnt[NTOT];

// ---------------------------------------------------------------------------
// m16n8k16 bf16 MMA (plain PTX, works on sm_103 base target)
__device__ __forceinline__ void mma16816(float* d, const uint32_t* a,
                                         uint32_t b0, uint32_t b1) {
    asm volatile(
        "mma.sync.aligned.m16n8k16.row.col.f32.bf16.bf16.f32 "
        "{%0,%1,%2,%3}, {%4,%5,%6,%7}, {%8,%9}, {%0,%1,%2,%3};"
        : "+f"(d[0]), "+f"(d[1]), "+f"(d[2]), "+f"(d[3])
        : "r"(a[0]), "r"(a[1]), "r"(a[2]), "r"(a[3]), "r"(b0), "r"(b1));
}

// Candidate insert with compaction-on-full (runmin monotonically decreases,
// so stale records are filtered; quad-shared runmin keeps counts tiny).
__device__ __forceinline__ void cand_insert(float s, int col, float* sc,
                                            unsigned short* cd, int& cnt,
                                            float& runmin, bool& ovf) {
    if (s < runmin + MARGIN) {
        if (cnt == LCAND) {
            int w = 0;
            for (int i = 0; i < LCAND; i++) {
                if (sc[i] < runmin + MARGIN) { sc[w] = sc[i]; cd[w] = cd[i]; w++; }
            }
            cnt = w;
        }
        if (cnt < LCAND) { sc[cnt] = s; cd[cnt] = (unsigned short)col; cnt++; }
        else ovf = true;
        if (s < runmin) runmin = s;
    }
}

// ---------------------------------------------------------------------------
// Prep: ||e_k||^2 serial (ref-style rounding) + zero usage
__global__ void vq_prep(const float* __restrict__ cb) {
    int k = blockIdx.x * 32 + threadIdx.x;
    const float* row = cb + k * C;
    float s = 0.f;
#pragma unroll
    for (int c = 0; c < C; c++) {
        float v = row[c];
        s = __fadd_rn(s, __fmul_rn(v, v));
    }
    d_enorm[k] = s;
    d_used[k] = 0;
}

// ---------------------------------------------------------------------------
// Tensor-pipe approximate scores + per-row candidate collection.
// 128 threads (4 warps); warp w owns rows w*32..w*32+31 (2 m16 tiles).
__global__ void __launch_bounds__(128)
vq_mma(const float* __restrict__ z, const float* __restrict__ cb) {
    __shared__ __nv_bfloat16 z_s[MT * ZS];   // 34816 B
    __shared__ __nv_bfloat16 b_s[NT * ZS];   // 8704 B
    __shared__ float en_s[NT];

    const int tid  = threadIdx.x;
    const int lane = tid & 31;
    const int wid  = tid >> 5;
    const int g    = lane >> 2;       // fragment group (row within tile)
    const int tq   = lane & 3;        // thread-in-quad
    const int n0   = blockIdx.x * MT;
    const int b    = n0 >> 12;
    const int hw0  = n0 & (HW - 1);
    const float* zb = z + (size_t)b * C * HW + hw0;

    // ---- stage z tile as bf16 [row][c] ----
    for (int p = tid; p < MT * (C / 2); p += 128) {
        int row = p & 127;            // coalesced along hw
        int cp  = p >> 7;             // c pair
        float a0 = zb[(size_t)(2 * cp)     * HW + row];
        float a1 = zb[(size_t)(2 * cp + 1) * HW + row];
        __nv_bfloat162 v = __floats2bfloat162_rn(a0, a1);
        *(uint32_t*)&z_s[row * ZS + 2 * cp] = *(uint32_t*)&v;
    }
    __syncthreads();

    // ---- A fragments, register resident: 2 m-tiles x 8 k-tiles x 4 regs ----
    uint32_t afr[2][8][4];
#pragma unroll
    for (int mt = 0; mt < 2; mt++) {
        const int r = wid * 32 + mt * 16 + g;
#pragma unroll
        for (int kt = 0; kt < 8; kt++) {
            const int k = kt * 16 + tq * 2;
            afr[mt][kt][0] = *(uint32_t*)&z_s[r * ZS + k];
            afr[mt][kt][1] = *(uint32_t*)&z_s[(r + 8) * ZS + k];
            afr[mt][kt][2] = *(uint32_t*)&z_s[r * ZS + k + 8];
            afr[mt][kt][3] = *(uint32_t*)&z_s[(r + 8) * ZS + k + 8];
        }
    }

    // per-lane state: 4 owned rows (slot = mt*2 + (e>>1)); the 4 lanes of a
    // quad own the SAME row (disjoint columns) -> runmin shareable via shfl.
    float runmin[4] = {INFINITY, INFINITY, INFINITY, INFINITY};
    int   cnt[4]    = {0, 0, 0, 0};
    bool  ovf[4]    = {false, false, false, false};
    float          sc[4][LCAND];
    unsigned short candl[4][LCAND];

    // ---- software-pipelined B: prefetch chunk's fp32 to regs, cvt on store ----
    float2 pre[16];
#pragma unroll
    for (int it = 0; it < 16; it++) {
        int p = it * 128 + tid;
        int row = p >> 6, cp = p & 63;
        pre[it] = *(const float2*)&cb[(size_t)row * C + 2 * cp];
    }
    float enp = (tid < NT) ? d_enorm[tid] : 0.f;

    for (int ch = 0; ch < NCH; ch++) {
#pragma unroll
        for (int it = 0; it < 16; it++) {
            int p = it * 128 + tid;
            int row = p >> 6, cp = p & 63;
            __nv_bfloat162 v = __floats2bfloat162_rn(pre[it].x, pre[it].y);
            *(uint32_t*)&b_s[row * ZS + 2 * cp] = *(uint32_t*)&v;
        }
        if (tid < NT) en_s[tid] = enp;
        __syncthreads();

        // issue next chunk's loads (hide L2 latency under MMA)
        if (ch + 1 < NCH) {
            const int k0n = (ch + 1) * NT;
#pragma unroll
            for (int it = 0; it < 16; it++) {
                int p = it * 128 + tid;
                int row = p >> 6, cp = p & 63;
                pre[it] = *(const float2*)&cb[(size_t)(k0n + row) * C + 2 * cp];
            }
            if (tid < NT) enp = d_enorm[k0n + tid];
        }

        const int k0 = ch * NT;
#pragma unroll
        for (int nt = 0; nt < 4; nt++) {
            const int nb = nt * 8;
            const float e0 = en_s[nb + 2 * tq];
            const float e1 = en_s[nb + 2 * tq + 1];
            uint32_t badr = (nb + g) * ZS + tq * 2;
            float acc[2][4] = {{0, 0, 0, 0}, {0, 0, 0, 0}};
#pragma unroll
            for (int kt = 0; kt < 8; kt++) {
                uint32_t b0 = *(uint32_t*)&b_s[badr + kt * 16];
                uint32_t b1 = *(uint32_t*)&b_s[badr + kt * 16 + 8];
                mma16816(acc[0], afr[0][kt], b0, b1);
                mma16816(acc[1], afr[1][kt], b0, b1);
            }
            const int col0 = k0 + nb + 2 * tq;
#pragma unroll
            for (int mt = 0; mt < 2; mt++) {
#pragma unroll
                for (int e = 0; e < 4; e++) {
                    const int slot = mt * 2 + (e >> 1);
                    const float en = (e & 1) ? e1 : e0;
                    float s = en - 2.f * acc[mt][e];
                    cand_insert(s, col0 + (e & 1), sc[slot], candl[slot],
                                cnt[slot], runmin[slot], ovf[slot]);
                }
            }
        }

        // Share runmin across the quad (same row) -> tighter threshold sooner.
#pragma unroll
        for (int slot = 0; slot < 4; slot++) {
            float r = runmin[slot];
            r = fminf(r, __shfl_xor_sync(0xffffffff, r, 1));
            r = fminf(r, __shfl_xor_sync(0xffffffff, r, 2));
            runmin[slot] = r;
        }
        __syncthreads();   // b_s/en_s reuse
    }

    // ---- final compaction against terminal runmin, then quad merge ----
    const int qbase = lane & ~3;
#pragma unroll
    for (int slot = 0; slot < 4; slot++) {
        int w = 0;
        for (int i = 0; i < cnt[slot]; i++) {
            if (sc[slot][i] < runmin[slot] + MARGIN) {
                sc[slot][w] = sc[slot][i];
                candl[slot][w] = candl[slot][i];
                w++;
            }
        }
        cnt[slot] = w;

        const int mt  = slot >> 1;
        const int sub = slot & 1;
        const int n   = n0 + wid * 32 + mt * 16 + g + sub * 8;
        int myc = ovf[slot] ? 100 : cnt[slot];
        int total = 0, off = 0;
#pragma unroll
        for (int j = 0; j < 4; j++) {
            int cj = __shfl_sync(0xffffffff, myc, qbase + j);
            total += cj;
            if (j < tq) off += cj;
        }
        if (total <= MAXCAND) {
            for (int i = 0; i < myc; i++)
                d_cand[(size_t)n * MAXCAND + off + i] = candl[slot][i];
        }
        if (tq == 0) d_ccnt[n] = total;
    }
}

// ---------------------------------------------------------------------------
// Exact rescore, WARP-PER-ROW: one lane per candidate (parallel), identical
// R5 arithmetic per candidate; overflow -> warp-cooperative full scan
// (32 codes/lane). Then gather + straight-through output + loss + usage.
__global__ void __launch_bounds__(128)
vq_rescore(const float* __restrict__ z, const float* __restrict__ cb,
           float* __restrict__ out) {
    __shared__ float z_s[C * TN];
    __shared__ float zn_s[TN];
    __shared__ int   idx_s[TN];
    __shared__ float red[128];

    const int tid  = threadIdx.x;
    const int lane = tid & 31;
    const int wid  = tid >> 5;
    const int n0   = blockIdx.x * TN;
    const int b    = n0 >> 12;
    const int hw0  = n0 & (HW - 1);
    const float* zb = z + (size_t)b * C * HW + hw0;

    for (int v = tid; v < C * TN / 4; v += 128) {
        int c  = v >> 4;
        int i4 = v & 15;
        float4 t = *reinterpret_cast<const float4*>(zb + (size_t)c * HW + i4 * 4);
        *reinterpret_cast<float4*>(&z_s[c * TN + i4 * 4]) = t;
    }
    __syncthreads();

    if (tid < TN) {
        float s = 0.f;
        for (int c = 0; c < C; c++) {
            float v = z_s[c * TN + tid];
            s = __fadd_rn(s, __fmul_rn(v, v));
        }
        zn_s[tid] = s;
    }
    __syncthreads();

    // Warp w handles rows [w*16, w*16+16). All lanes of a warp read the same
    // z row from z_s (LDS broadcast).
    for (int rr = 0; rr < TN / 4; rr++) {
        const int row = wid * (TN / 4) + rr;
        const int n   = n0 + row;
        const int cnt = d_ccnt[n];
        const float zn = zn_s[row];

        float s = INFINITY;
        int   k = KC;
        if (cnt <= MAXCAND) {
            if (lane < cnt) {
                k = d_cand[(size_t)n * MAXCAND + lane];
                const float* e = cb + (size_t)k * C;
                float dot = 0.f;
#pragma unroll 4
                for (int c = 0; c < C; c++)
                    dot = fmaf(__ldg(&e[c]), z_s[c * TN + row], dot);
                float t1 = __fadd_rn(zn, __ldg(&d_enorm[k]));
                s = __fadd_rn(t1, __fmul_rn(-2.f, dot));
            }
        } else {
            // overflow: warp-cooperative exact full scan, 32 codes per lane
            for (int j = lane; j < KC; j += 32) {
                const float* e = cb + (size_t)j * C;
                float dot = 0.f;
#pragma unroll 4
                for (int c = 0; c < C; c++)
                    dot = fmaf(__ldg(&e[c]), z_s[c * TN + row], dot);
                float t1 = __fadd_rn(zn, __ldg(&d_enorm[j]));
                float sj = __fadd_rn(t1, __fmul_rn(-2.f, dot));
                if (sj < s) { s = sj; k = j; }   // ascending within lane
            }
        }
        // warp reduce: min score, ties -> smallest k (== jnp.argmin first-min)
#pragma unroll
        for (int m = 16; m >= 1; m >>= 1) {
            float so = __shfl_xor_sync(0xffffffff, s, m);
            int   ko = __shfl_xor_sync(0xffffffff, k, m);
            if (so < s || (so == s && ko < k)) { s = so; k = ko; }
        }
        if (lane == 0) {
            idx_s[row] = k;
            d_used[k] = 1;
        }
    }
    __syncthreads();

    float* ob = out + (size_t)b * C * HW + hw0;
    float lsum = 0.f;
    for (int p = tid; p < TN * C; p += 128) {
        int row = p & (TN - 1);
        int c   = p >> 6;
        float zq = __ldg(&cb[(size_t)idx_s[row] * C + c]);
        float zv = z_s[c * TN + row];
        float d  = __fadd_rn(zq, -zv);
        ob[(size_t)c * HW + row] = __fadd_rn(zv, d);
        lsum += d * d;
    }

    red[tid] = lsum;
    __syncthreads();
#pragma unroll
    for (int s = 64; s > 0; s >>= 1) {
        if (tid < s) red[tid] += red[tid + s];
        __syncthreads();
    }
    if (tid == 0) d_partials[blockIdx.x] = red[0];
}

// ---------------------------------------------------------------------------
__global__ void vq_final(float* __restrict__ out, int out_size) {
    __shared__ float fred[256];
    __shared__ int   ired[256];
    const int t = threadIdx.x;

    float fs = 0.f;
#pragma unroll
    for (int p = t; p < NBLK; p += 256) fs += d_partials[p];
    int cnt = 0;
#pragma unroll
    for (int k = t; k < KC; k += 256) cnt += d_used[k];
    fred[t] = fs;
    ired[t] = cnt;
    __syncthreads();
#pragma unroll
    for (int s = 128; s > 0; s >>= 1) {
        if (t < s) { fred[t] += fred[t + s]; ired[t] += ired[t + s]; }
        __syncthreads();
    }
    if (t == 0 && out_size >= M_ZQ + 2) {
        float mse = fred[0] / (float)((size_t)NTOT * C);
        out[M_ZQ]     = 1.25f * mse;
        out[M_ZQ + 1] = (float)ired[0] / (float)KC;
    }
}

// ---------------------------------------------------------------------------
extern "C" void kernel_launch(void* const* d_in, const int* in_sizes, int n_in,
                              void* d_out, int out_size) {
    const float* z;
    const float* cb;
    if (in_sizes[0] == KC * C) {
        cb = (const float*)d_in[0];
        z  = (const float*)d_in[1];
    } else {
        z  = (const float*)d_in[0];
        cb = (const float*)d_in[1];
    }
    float* out = (float*)d_out;

    vq_prep<<<KC / 32, 32>>>(cb);
    vq_mma<<<GRID_MMA, 128>>>(z, cb);
    vq_rescore<<<NBLK, 128>>>(z, cb, out);
    vq_final<<<1, 256>>>(out, out_size);
}

// round 13
// speedup vs baseline: 14.9058x; 1.5095x over previous
#include <cuda_runtime.h>
#include <cuda_bf16.h>
#include <math.h>
#include <stdint.h>

// z (16,128,64,64) fp32, codebook (1024,128) fp32
#define C      128
#define KC     1024
#define BATCH  16
#define HW     4096
#define NTOT   (BATCH * HW)     // 65536
#define M_ZQ   (NTOT * C)       // 8388608
#define MT     64               // rows per CTA
#define NT     32               // codes per chunk
#define NCH    (KC / NT)        // 32 chunks
#define NBLK   (NTOT / MT)      // 1024 CTAs
#define MARGIN 1e-3f            // > 2x worst-case bf16 score error (~4.4e-4)
#define LCAND  8                // per-lane candidate cap (with compaction)
#define ZSF    129              // z_s floats per row (128 + 1 pad)
#define BSH    136              // b_s halfs per row (128 + 8 pad)

// Scratch (no allocs allowed)
__device__ float d_enorm[KC];
__device__ int   d_used[KC];
__device__ float d_partials[NBLK];

// ---------------------------------------------------------------------------
// m16n8k16 bf16 MMA (plain PTX, works on sm_103 base target)
__device__ __forceinline__ void mma16816(float* d, const uint32_t* a,
                                         uint32_t b0, uint32_t b1) {
    asm volatile(
        "mma.sync.aligned.m16n8k16.row.col.f32.bf16.bf16.f32 "
        "{%0,%1,%2,%3}, {%4,%5,%6,%7}, {%8,%9}, {%0,%1,%2,%3};"
        : "+f"(d[0]), "+f"(d[1]), "+f"(d[2]), "+f"(d[3])
        : "r"(a[0]), "r"(a[1]), "r"(a[2]), "r"(a[3]), "r"(b0), "r"(b1));
}

// Candidate insert with compaction-on-full (runmin only decreases; stale
// records get filtered out on demand).
__device__ __forceinline__ void cand_insert(float s, int col, float* sc,
                                            unsigned short* cd, int& cnt,
                                            float& runmin, bool& ovf) {
    if (s < runmin + MARGIN) {
        if (cnt == LCAND) {
            int w = 0;
            for (int i = 0; i < LCAND; i++) {
                if (sc[i] < runmin + MARGIN) { sc[w] = sc[i]; cd[w] = cd[i]; w++; }
            }
            cnt = w;
        }
        if (cnt < LCAND) { sc[cnt] = s; cd[cnt] = (unsigned short)col; cnt++; }
        else ovf = true;
        if (s < runmin) runmin = s;
    }
}

// Exact score, bit-identical to the validated round-5 arithmetic.
__device__ __forceinline__ float exact_score(const float* __restrict__ cb,
                                             const float* zrow, float zn, int k) {
    const float* e = cb + (size_t)k * C;
    float dot = 0.f;
#pragma unroll 4
    for (int c = 0; c < C; c++)
        dot = fmaf(__ldg(&e[c]), zrow[c], dot);
    float t1 = __fadd_rn(zn, __ldg(&d_enorm[k]));
    return __fadd_rn(t1, __fmul_rn(-2.f, dot));
}

// ---------------------------------------------------------------------------
// Prep: ||e_k||^2 serial (ref-style rounding) + zero usage
__global__ void vq_prep(const float* __restrict__ cb) {
    int k = blockIdx.x * 32 + threadIdx.x;
    const float* row = cb + k * C;
    float s = 0.f;
#pragma unroll
    for (int c = 0; c < C; c++) {
        float v = row[c];
        s = __fadd_rn(s, __fmul_rn(v, v));
    }
    d_enorm[k] = s;
    d_used[k] = 0;
}

// ---------------------------------------------------------------------------
// Fused: HMMA approx scores -> in-register candidates -> exact rescore from
// fp32 smem -> gather + straight-through output + loss partial + usage.
// 128 threads (4 warps); warp w owns rows [w*16, w*16+16).
__global__ void __launch_bounds__(128)
vq_fused(const float* __restrict__ z, const float* __restrict__ cb,
         float* __restrict__ out) {
    __shared__ float         z_s[MT * ZSF];   // fp32 z tile, 33024 B
    __shared__ __nv_bfloat16 b_s[NT * BSH];   // bf16 codebook chunk, 8704 B
    __shared__ float en_s[NT];
    __shared__ float zn_s[MT];
    __shared__ int   idx_s[MT];
    __shared__ float red[128];                // total ~43.2 KB static

    const int tid  = threadIdx.x;
    const int lane = tid & 31;
    const int wid  = tid >> 5;
    const int g    = lane >> 2;       // fragment group (row within m16 tile)
    const int tq   = lane & 3;        // thread-in-quad (owns cols 2tq,2tq+1 mod 8)
    const int n0   = blockIdx.x * MT;
    const int b    = n0 >> 12;        // MT divides HW -> tile within one batch
    const int hw0  = n0 & (HW - 1);
    const float* zb = z + (size_t)b * C * HW + hw0;

    // ---- 1) load z tile fp32 -> z_s[row][c] (stride 129: conflict-free both ways)
    for (int p = tid; p < MT * C; p += 128) {
        int row = p & (MT - 1);       // coalesced along hw
        int c   = p >> 6;
        z_s[row * ZSF + c] = zb[(size_t)c * HW + row];
    }
    __syncthreads();

    // ---- 2) ||z||^2 serial ascending c (ref-style) + bf16 A fragments
    if (tid < MT) {
        float s = 0.f;
        for (int c = 0; c < C; c++) {
            float v = z_s[tid * ZSF + c];
            s = __fadd_rn(s, __fmul_rn(v, v));
        }
        zn_s[tid] = s;
    }

    const int r0 = wid * 16 + g;      // rows owned by this lane: r0, r0+8
    const int r1 = r0 + 8;
    uint32_t afr[8][4];
#pragma unroll
    for (int kt = 0; kt < 8; kt++) {
        const int k = kt * 16 + tq * 2;
        __nv_bfloat162 v0 = __floats2bfloat162_rn(z_s[r0 * ZSF + k],     z_s[r0 * ZSF + k + 1]);
        __nv_bfloat162 v1 = __floats2bfloat162_rn(z_s[r1 * ZSF + k],     z_s[r1 * ZSF + k + 1]);
        __nv_bfloat162 v2 = __floats2bfloat162_rn(z_s[r0 * ZSF + k + 8], z_s[r0 * ZSF + k + 9]);
        __nv_bfloat162 v3 = __floats2bfloat162_rn(z_s[r1 * ZSF + k + 8], z_s[r1 * ZSF + k + 9]);
        afr[kt][0] = *(uint32_t*)&v0;
        afr[kt][1] = *(uint32_t*)&v1;
        afr[kt][2] = *(uint32_t*)&v2;
        afr[kt][3] = *(uint32_t*)&v3;
    }
    __syncthreads();

    // per-lane candidate state: 2 slots (rows r0, r1); the 4 lanes of a quad
    // own the SAME two rows (disjoint columns) -> runmin shared via shfl.
    float runmin[2] = {INFINITY, INFINITY};
    int   cnt[2]    = {0, 0};
    bool  ovf[2]    = {false, false};
    float          sc[2][LCAND];
    unsigned short candl[2][LCAND];

    // ---- 3) chunk loop: stage B (fp32->bf16), HMMA, collect candidates
    float2 pre[16];
#pragma unroll
    for (int it = 0; it < 16; it++) {
        int p = it * 128 + tid;
        int row = p >> 6, cp = p & 63;
        pre[it] = *(const float2*)&cb[(size_t)row * C + 2 * cp];
    }
    float enp = (tid < NT) ? d_enorm[tid] : 0.f;

    for (int ch = 0; ch < NCH; ch++) {
#pragma unroll
        for (int it = 0; it < 16; it++) {
            int p = it * 128 + tid;
            int row = p >> 6, cp = p & 63;
            __nv_bfloat162 v = __floats2bfloat162_rn(pre[it].x, pre[it].y);
            *(uint32_t*)&b_s[row * BSH + 2 * cp] = *(uint32_t*)&v;
        }
        if (tid < NT) en_s[tid] = enp;
        __syncthreads();

        if (ch + 1 < NCH) {
            const int k0n = (ch + 1) * NT;
#pragma unroll
            for (int it = 0; it < 16; it++) {
                int p = it * 128 + tid;
                int row = p >> 6, cp = p & 63;
                pre[it] = *(const float2*)&cb[(size_t)(k0n + row) * C + 2 * cp];
            }
            if (tid < NT) enp = d_enorm[k0n + tid];
        }

        const int k0 = ch * NT;
#pragma unroll
        for (int nt = 0; nt < 4; nt++) {
            const int nb = nt * 8;
            const float e0 = en_s[nb + 2 * tq];
            const float e1 = en_s[nb + 2 * tq + 1];
            const uint32_t badr = (nb + g) * BSH + tq * 2;
            float acc[4] = {0, 0, 0, 0};
#pragma unroll
            for (int kt = 0; kt < 8; kt++) {
                uint32_t b0 = *(uint32_t*)&b_s[badr + kt * 16];
                uint32_t b1 = *(uint32_t*)&b_s[badr + kt * 16 + 8];
                mma16816(acc, afr[kt], b0, b1);
            }
            const int col0 = k0 + nb + 2 * tq;
#pragma unroll
            for (int e = 0; e < 4; e++) {
                const int slot = e >> 1;          // 0: row r0, 1: row r1
                const float en = (e & 1) ? e1 : e0;
                float s = en - 2.f * acc[e];
                cand_insert(s, col0 + (e & 1), sc[slot], candl[slot],
                            cnt[slot], runmin[slot], ovf[slot]);
            }
        }

        // share runmin across the quad (same rows) -> tighter threshold sooner
#pragma unroll
        for (int slot = 0; slot < 2; slot++) {
            float r = runmin[slot];
            r = fminf(r, __shfl_xor_sync(0xffffffff, r, 1));
            r = fminf(r, __shfl_xor_sync(0xffffffff, r, 2));
            runmin[slot] = r;
        }
        __syncthreads();   // b_s/en_s reuse
    }

    // ---- 4) exact rescore per owned row (candidates in regs, z fp32 in smem)
#pragma unroll
    for (int slot = 0; slot < 2; slot++) {
        const int row = (slot == 0) ? r0 : r1;
        const float* zrow = &z_s[row * ZSF];
        const float zn = zn_s[row];

        float best = INFINITY;
        int   bk   = KC;
        if (!ovf[slot]) {
            for (int i = 0; i < cnt[slot]; i++) {
                if (sc[slot][i] < runmin[slot] + MARGIN) {   // final prune
                    int k = candl[slot][i];                  // ascending order
                    float s = exact_score(cb, zrow, zn, k);
                    if (s < best || (s == best && k < bk)) { best = s; bk = k; }
                }
            }
        } else {
            // overflow (~never): exact rescan of THIS lane's 256 columns
            for (int base = 0; base < KC / 8; base++) {
#pragma unroll
                for (int e = 0; e < 2; e++) {
                    int k = base * 8 + 2 * tq + e;
                    float s = exact_score(cb, zrow, zn, k);
                    if (s < best || (s == best && k < bk)) { best = s; bk = k; }
                }
            }
        }
        // quad reduce: min score, ties -> smallest k (== jnp.argmin first-min)
#pragma unroll
        for (int m = 1; m <= 2; m <<= 1) {
            float so = __shfl_xor_sync(0xffffffff, best, m);
            int   ko = __shfl_xor_sync(0xffffffff, bk, m);
            if (so < best || (so == best && ko < bk)) { best = so; bk = ko; }
        }
        if (tq == 0) {
            idx_s[row] = bk;
            d_used[bk] = 1;   // benign race: all writers store 1
        }
    }
    __syncthreads();

    // ---- 5) gather + straight-through write + loss partial
    float* ob = out + (size_t)b * C * HW + hw0;
    float lsum = 0.f;
    for (int p = tid; p < MT * C; p += 128) {
        int row = p & (MT - 1);
        int c   = p >> 6;
        float zq = __ldg(&cb[(size_t)idx_s[row] * C + c]);
        float zv = z_s[row * ZSF + c];
        float d  = __fadd_rn(zq, -zv);                 // fl(z_q - z)
        ob[(size_t)c * HW + row] = __fadd_rn(zv, d);   // fl(z + fl(z_q - z))
        lsum += d * d;
    }

    red[tid] = lsum;
    __syncthreads();
#pragma unroll
    for (int s = 64; s > 0; s >>= 1) {
        if (tid < s) red[tid] += red[tid + s];
        __syncthreads();
    }
    if (tid == 0) d_partials[blockIdx.x] = red[0];
}

// ---------------------------------------------------------------------------
__global__ void vq_final(float* __restrict__ out, int out_size) {
    __shared__ float fred[256];
    __shared__ int   ired[256];
    const int t = threadIdx.x;

    float fs = 0.f;
#pragma unroll
    for (int p = t; p < NBLK; p += 256) fs += d_partials[p];
    int cnt = 0;
#pragma unroll
    for (int k = t; k < KC; k += 256) cnt += d_used[k];
    fred[t] = fs;
    ired[t] = cnt;
    __syncthreads();
#pragma unroll
    for (int s = 128; s > 0; s >>= 1) {
        if (t < s) { fred[t] += fred[t + s]; ired[t] += ired[t + s]; }
        __syncthreads();
    }
    if (t == 0 && out_size >= M_ZQ + 2) {
        float mse = fred[0] / (float)((size_t)NTOT * C);
        out[M_ZQ]     = 1.25f * mse;
        out[M_ZQ + 1] = (float)ired[0] / (float)KC;
    }
}

// ---------------------------------------------------------------------------
extern "C" void kernel_launch(void* const* d_in, const int* in_sizes, int n_in,
                              void* d_out, int out_size) {
    const float* z;
    const float* cb;
    if (in_sizes[0] == KC * C) {
        cb = (const float*)d_in[0];
        z  = (const float*)d_in[1];
    } else {
        z  = (const float*)d_in[0];
        cb = (const float*)d_in[1];
    }
    float* out = (float*)d_out;

    vq_prep<<<KC / 32, 32>>>(cb);
    vq_fused<<<NBLK, 128>>>(z, cb, out);
    vq_final<<<1, 256>>>(out, out_size);
}

// round 15
// speedup vs baseline: 15.6396x; 1.0492x over previous
#include <cuda_runtime.h>
#include <cuda_bf16.h>
#include <math.h>
#include <stdint.h>

// z (16,128,64,64) fp32, codebook (1024,128) fp32
#define C      128
#define KC     1024
#define BATCH  16
#define HW     4096
#define NTOT   (BATCH * HW)     // 65536
#define M_ZQ   (NTOT * C)       // 8388608
#define MT     64               // rows per CTA
#define NT     32               // codes per chunk
#define NCH    (KC / NT)        // 32 chunks
#define NBLK   (NTOT / MT)      // 1024 CTAs
#define MARGIN 1e-3f            // > 2x worst-case bf16 score error (~4.4e-4)
#define LCAND  8                // per-lane candidate cap (with compaction)
#define ZSF    129              // z_s floats per row (128 + 1 pad)
#define BSH    136              // b_s halfs per row (128 + 8 pad)

// Scratch (no allocs allowed)
__device__ float d_enorm[KC];
__device__ int   d_used[KC];
__device__ float d_partials[NBLK];
__device__ __nv_bfloat16 d_cbB[KC * C];   // bf16 codebook, chunk-linear [k][c]

// ---------------------------------------------------------------------------
// m16n8k16 bf16 MMA (plain PTX, works on sm_103 base target)
__device__ __forceinline__ void mma16816(float* d, const uint32_t* a,
                                         uint32_t b0, uint32_t b1) {
    asm volatile(
        "mma.sync.aligned.m16n8k16.row.col.f32.bf16.bf16.f32 "
        "{%0,%1,%2,%3}, {%4,%5,%6,%7}, {%8,%9}, {%0,%1,%2,%3};"
        : "+f"(d[0]), "+f"(d[1]), "+f"(d[2]), "+f"(d[3])
        : "r"(a[0]), "r"(a[1]), "r"(a[2]), "r"(a[3]), "r"(b0), "r"(b1));
}

// Candidate insert with compaction-on-full (runmin only decreases; stale
// records get filtered out on demand).
__device__ __forceinline__ void cand_insert(float s, int col, float* sc,
                                            unsigned short* cd, int& cnt,
                                            float& runmin, bool& ovf) {
    if (s < runmin + MARGIN) {
        if (cnt == LCAND) {
            int w = 0;
            for (int i = 0; i < LCAND; i++) {
                if (sc[i] < runmin + MARGIN) { sc[w] = sc[i]; cd[w] = cd[i]; w++; }
            }
            cnt = w;
        }
        if (cnt < LCAND) { sc[cnt] = s; cd[cnt] = (unsigned short)col; cnt++; }
        else ovf = true;
        if (s < runmin) runmin = s;
    }
}

// Exact score, bit-identical to the validated round-5 arithmetic.
__device__ __forceinline__ float exact_score(const float* __restrict__ cb,
                                             const float* zrow, float zn, int k) {
    const float* e = cb + (size_t)k * C;
    float dot = 0.f;
#pragma unroll 4
    for (int c = 0; c < C; c++)
        dot = fmaf(__ldg(&e[c]), zrow[c], dot);
    float t1 = __fadd_rn(zn, __ldg(&d_enorm[k]));
    return __fadd_rn(t1, __fmul_rn(-2.f, dot));
}

// ---------------------------------------------------------------------------
// Prep A: ||e_k||^2 serial (ref-style rounding) + zero usage
__global__ void vq_prep(const float* __restrict__ cb) {
    int k = blockIdx.x * 32 + threadIdx.x;
    const float* row = cb + k * C;
    float s = 0.f;
#pragma unroll
    for (int c = 0; c < C; c++) {
        float v = row[c];
        s = __fadd_rn(s, __fmul_rn(v, v));
    }
    d_enorm[k] = s;
    d_used[k] = 0;
}

// Prep B: codebook fp32 -> bf16 once (saves 1024x redundant cvt in the mainloop)
__global__ void vq_cvt(const float* __restrict__ cb) {
    int i = blockIdx.x * 256 + threadIdx.x;        // 0 .. 65535 (bf162 pairs)
    float2 v = *(const float2*)&cb[2 * i];
    __nv_bfloat162 h = __floats2bfloat162_rn(v.x, v.y);
    *(uint32_t*)&d_cbB[2 * i] = *(uint32_t*)&h;
}

// ---------------------------------------------------------------------------
// Fused: HMMA approx scores -> in-register candidates -> exact rescore from
// fp32 smem -> gather + straight-through output + loss partial + usage.
// 128 threads (4 warps); warp w owns rows [w*16, w*16+16).
__global__ void __launch_bounds__(128, 4)
vq_fused(const float* __restrict__ z, const float* __restrict__ cb,
         float* __restrict__ out) {
    __shared__ float         z_s[MT * ZSF];   // fp32 z tile, 33024 B
    __shared__ __nv_bfloat16 b_s[NT * BSH];   // bf16 codebook chunk, 8704 B
    __shared__ float en_s[NT];
    __shared__ float zn_s[MT];
    __shared__ int   idx_s[MT];
    __shared__ float red[128];                // total ~43.2 KB static

    const int tid  = threadIdx.x;
    const int lane = tid & 31;
    const int wid  = tid >> 5;
    const int g    = lane >> 2;       // fragment group (row within m16 tile)
    const int tq   = lane & 3;        // thread-in-quad (owns cols 2tq,2tq+1 mod 8)
    const int n0   = blockIdx.x * MT;
    const int b    = n0 >> 12;        // MT divides HW -> tile within one batch
    const int hw0  = n0 & (HW - 1);
    const float* zb = z + (size_t)b * C * HW + hw0;

    // ---- 1) load z tile fp32 -> z_s[row][c] (stride 129: conflict-free)
    for (int p = tid; p < MT * C; p += 128) {
        int row = p & (MT - 1);       // coalesced along hw
        int c   = p >> 6;
        z_s[row * ZSF + c] = zb[(size_t)c * HW + row];
    }
    __syncthreads();

    // ---- 2) ||z||^2 serial ascending c (ref-style) + bf16 A fragments
    if (tid < MT) {
        float s = 0.f;
        for (int c = 0; c < C; c++) {
            float v = z_s[tid * ZSF + c];
            s = __fadd_rn(s, __fmul_rn(v, v));
        }
        zn_s[tid] = s;
    }

    const int r0 = wid * 16 + g;      // rows owned by this lane: r0, r0+8
    const int r1 = r0 + 8;
    uint32_t afr[8][4];
#pragma unroll
    for (int kt = 0; kt < 8; kt++) {
        const int k = kt * 16 + tq * 2;
        __nv_bfloat162 v0 = __floats2bfloat162_rn(z_s[r0 * ZSF + k],     z_s[r0 * ZSF + k + 1]);
        __nv_bfloat162 v1 = __floats2bfloat162_rn(z_s[r1 * ZSF + k],     z_s[r1 * ZSF + k + 1]);
        __nv_bfloat162 v2 = __floats2bfloat162_rn(z_s[r0 * ZSF + k + 8], z_s[r0 * ZSF + k + 9]);
        __nv_bfloat162 v3 = __floats2bfloat162_rn(z_s[r1 * ZSF + k + 8], z_s[r1 * ZSF + k + 9]);
        afr[kt][0] = *(uint32_t*)&v0;
        afr[kt][1] = *(uint32_t*)&v1;
        afr[kt][2] = *(uint32_t*)&v2;
        afr[kt][3] = *(uint32_t*)&v3;
    }
    __syncthreads();

    // per-lane candidate state: 2 slots (rows r0, r1); the 4 lanes of a quad
    // own the SAME two rows (disjoint columns) -> runmin shared via shfl.
    float runmin[2] = {INFINITY, INFINITY};
    int   cnt[2]    = {0, 0};
    bool  ovf[2]    = {false, false};
    float          sc[2][LCAND];
    unsigned short candl[2][LCAND];

    // ---- 3) chunk loop: copy pre-converted bf16 B (uint4), HMMA, candidates
    // chunk ch occupies d_cbB[ch*NT*C .. ) = 8192 B = 512 uint4
    uint4 pre[4];
#pragma unroll
    for (int it = 0; it < 4; it++)
        pre[it] = ((const uint4*)d_cbB)[it * 128 + tid];
    float enp = (tid < NT) ? d_enorm[tid] : 0.f;

    for (int ch = 0; ch < NCH; ch++) {
#pragma unroll
        for (int it = 0; it < 4; it++) {
            int idx = it * 128 + tid;        // uint4 index within chunk
            int row = idx >> 4;              // 16 uint4 per 128-half row
            int c16 = idx & 15;
            *(uint4*)&b_s[row * BSH + c16 * 8] = pre[it];
        }
        if (tid < NT) en_s[tid] = enp;
        __syncthreads();

        if (ch + 1 < NCH) {
            const uint4* src = (const uint4*)(d_cbB + (size_t)(ch + 1) * NT * C);
#pragma unroll
            for (int it = 0; it < 4; it++)
                pre[it] = src[it * 128 + tid];
            if (tid < NT) enp = d_enorm[(ch + 1) * NT + tid];
        }

        const int k0 = ch * NT;
#pragma unroll
        for (int nt = 0; nt < 4; nt++) {
            const int nb = nt * 8;
            const float e0 = en_s[nb + 2 * tq];
            const float e1 = en_s[nb + 2 * tq + 1];
            const uint32_t badr = (nb + g) * BSH + tq * 2;
            float acc[4] = {0, 0, 0, 0};
#pragma unroll
            for (int kt = 0; kt < 8; kt++) {
                uint32_t b0 = *(uint32_t*)&b_s[badr + kt * 16];
                uint32_t b1 = *(uint32_t*)&b_s[badr + kt * 16 + 8];
                mma16816(acc, afr[kt], b0, b1);
            }
            const int col0 = k0 + nb + 2 * tq;
#pragma unroll
            for (int e = 0; e < 4; e++) {
                const int slot = e >> 1;          // 0: row r0, 1: row r1
                const float en = (e & 1) ? e1 : e0;
                float s = en - 2.f * acc[e];
                cand_insert(s, col0 + (e & 1), sc[slot], candl[slot],
                            cnt[slot], runmin[slot], ovf[slot]);
            }
        }

        // share runmin across the quad (same rows) -> tighter threshold sooner
#pragma unroll
        for (int slot = 0; slot < 2; slot++) {
            float r = runmin[slot];
            r = fminf(r, __shfl_xor_sync(0xffffffff, r, 1));
            r = fminf(r, __shfl_xor_sync(0xffffffff, r, 2));
            runmin[slot] = r;
        }
        __syncthreads();   // b_s/en_s reuse
    }

    // ---- 4) exact rescore per owned row (candidates in regs, z fp32 in smem)
#pragma unroll
    for (int slot = 0; slot < 2; slot++) {
        const int row = (slot == 0) ? r0 : r1;
        const float* zrow = &z_s[row * ZSF];
        const float zn = zn_s[row];

        float best = INFINITY;
        int   bk   = KC;
        if (!ovf[slot]) {
            for (int i = 0; i < cnt[slot]; i++) {
                if (sc[slot][i] < runmin[slot] + MARGIN) {   // final prune
                    int k = candl[slot][i];                  // ascending order
                    float s = exact_score(cb, zrow, zn, k);
                    if (s < best || (s == best && k < bk)) { best = s; bk = k; }
                }
            }
        } else {
            // overflow (~never): exact rescan of THIS lane's 256 columns
            for (int base = 0; base < KC / 8; base++) {
#pragma unroll
                for (int e = 0; e < 2; e++) {
                    int k = base * 8 + 2 * tq + e;
                    float s = exact_score(cb, zrow, zn, k);
                    if (s < best || (s == best && k < bk)) { best = s; bk = k; }
                }
            }
        }
        // quad reduce: min score, ties -> smallest k (== jnp.argmin first-min)
#pragma unroll
        for (int m = 1; m <= 2; m <<= 1) {
            float so = __shfl_xor_sync(0xffffffff, best, m);
            int   ko = __shfl_xor_sync(0xffffffff, bk, m);
            if (so < best || (so == best && ko < bk)) { best = so; bk = ko; }
        }
        if (tq == 0) {
            idx_s[row] = bk;
            d_used[bk] = 1;   // benign race: all writers store 1
        }
    }
    __syncthreads();

    // ---- 5) gather + straight-through write + loss partial
    float* ob = out + (size_t)b * C * HW + hw0;
    float lsum = 0.f;
    for (int p = tid; p < MT * C; p += 128) {
        int row = p & (MT - 1);
        int c   = p >> 6;
        float zq = __ldg(&cb[(size_t)idx_s[row] * C + c]);
        float zv = z_s[row * ZSF + c];
        float d  = __fadd_rn(zq, -zv);                 // fl(z_q - z)
        ob[(size_t)c * HW + row] = __fadd_rn(zv, d);   // fl(z + fl(z_q - z))
        lsum += d * d;
    }

    red[tid] = lsum;
    __syncthreads();
#pragma unroll
    for (int s = 64; s > 0; s >>= 1) {
        if (tid < s) red[tid] += red[tid + s];
        __syncthreads();
    }
    if (tid == 0) d_partials[blockIdx.x] = red[0];
}

// ---------------------------------------------------------------------------
__global__ void vq_final(float* __restrict__ out, int out_size) {
    __shared__ float fred[256];
    __shared__ int   ired[256];
    const int t = threadIdx.x;

    float fs = 0.f;
#pragma unroll
    for (int p = t; p < NBLK; p += 256) fs += d_partials[p];
    int cnt = 0;
#pragma unroll
    for (int k = t; k < KC; k += 256) cnt += d_used[k];
    fred[t] = fs;
    ired[t] = cnt;
    __syncthreads();
#pragma unroll
    for (int s = 128; s > 0; s >>= 1) {
        if (t < s) { fred[t] += fred[t + s]; ired[t] += ired[t + s]; }
        __syncthreads();
    }
    if (t == 0 && out_size >= M_ZQ + 2) {
        float mse = fred[0] / (float)((size_t)NTOT * C);
        out[M_ZQ]     = 1.25f * mse;
        out[M_ZQ + 1] = (float)ired[0] / (float)KC;
    }
}

// ---------------------------------------------------------------------------
extern "C" void kernel_launch(void* const* d_in, const int* in_sizes, int n_in,
                              void* d_out, int out_size) {
    const float* z;
    const float* cb;
    if (in_sizes[0] == KC * C) {
        cb = (const float*)d_in[0];
        z  = (const float*)d_in[1];
    } else {
        z  = (const float*)d_in[0];
        cb = (const float*)d_in[1];
    }
    float* out = (float*)d_out;

    vq_prep<<<KC / 32, 32>>>(cb);
    vq_cvt<<<(KC * C / 2) / 256, 256>>>(cb);
    vq_fused<<<NBLK, 128>>>(z, cb, out);
    vq_final<<<1, 256>>>(out, out_size);
}